// round 16
// baseline (speedup 1.0000x reference)
#include <cuda_runtime.h>
#include <cuda_bf16.h>
#include <math.h>
#include <stdint.h>

// Problem dims
#define NTOK 16384      // B*S
#define DIM  4096       // D (K of both GEMMs)
#define HID  2048       // H (N of GEMM1)
#define NEXP 64
#define TOPK 3

// Output layout (float32, concatenated flattened reference outputs)
#define OFF_W 0
#define OFF_I (NTOK * TOPK)
#define OFF_M (2 * NTOK * TOPK)
#define OFF_K (2 * NTOK * TOPK + NTOK * NEXP)

// Scratch (device globals)
#define XPLANE ((size_t)NTOK * DIM)
#define WPLANE ((size_t)HID * DIM)
#define GPLANE ((size_t)NEXP * DIM)
#define FLAG_CAP 4096
#define RTOK 8
#define RCB  8           // repair column blocks (HID/256)
#define NZT  16          // z-partial tiles (HID/128)
__device__ __align__(16) __nv_bfloat16 g_xs[XPLANE];    // 134 MB: x hi plane
__device__ __align__(16) __nv_bfloat16 g_xs2[XPLANE];   // 134 MB: x lo plane
__device__ __align__(16) __nv_bfloat16 g_w1t[WPLANE];   // 17 MB: W1^T bf16 [N][K]
__device__ __align__(16) __nv_bfloat16 g_wt1[GPLANE];   // 0.5 MB: W^T hi [E][K]
__device__ __align__(16) __nv_bfloat16 g_wt2[GPLANE];   // 0.5 MB: W^T lo [E][K]
__device__ float g_zp[(size_t)NTOK * NZT];              // 1 MB: z partials per n-tile
__device__ float g_logits[(size_t)NTOK * NEXP];         // 4 MB
__device__ int   g_kdyn[NTOK];
__device__ int   g_nflag;                               // z-boundary flags
__device__ int   g_flaglist[FLAG_CAP];
__device__ int   g_nlflag;                              // logit-margin flags
__device__ int   g_lflaglist[FLAG_CAP];
__device__ double g_zpart[FLAG_CAP][RCB];

// ---------------------------------------------------------------------------
// PTX helpers (baseline sm_80+ ISA)
// ---------------------------------------------------------------------------
__device__ __forceinline__ uint32_t smem_u32(const void* p) {
    uint32_t a;
    asm("{ .reg .u64 t; cvta.to.shared.u64 t, %1; cvt.u32.u64 %0, t; }" : "=r"(a) : "l"(p));
    return a;
}
__device__ __forceinline__ void cp_async16(uint32_t dst, const void* src) {
    asm volatile("cp.async.cg.shared.global [%0], [%1], 16;" :: "r"(dst), "l"(src));
}
__device__ __forceinline__ void cp_commit() {
    asm volatile("cp.async.commit_group;");
}
template <int N>
__device__ __forceinline__ void cp_wait() {
    asm volatile("cp.async.wait_group %0;" :: "n"(N));
}
__device__ __forceinline__ void ldmatrix_x4(uint32_t& r0, uint32_t& r1, uint32_t& r2, uint32_t& r3,
                                            uint32_t addr) {
    asm volatile("ldmatrix.sync.aligned.m8n8.x4.shared.b16 {%0,%1,%2,%3}, [%4];"
                 : "=r"(r0), "=r"(r1), "=r"(r2), "=r"(r3) : "r"(addr));
}
__device__ __forceinline__ void mma_bf16(float* c, const uint32_t* a, const uint32_t* b) {
    asm volatile(
        "mma.sync.aligned.m16n8k16.row.col.f32.bf16.bf16.f32 "
        "{%0,%1,%2,%3}, {%4,%5,%6,%7}, {%8,%9}, {%0,%1,%2,%3};"
        : "+f"(c[0]), "+f"(c[1]), "+f"(c[2]), "+f"(c[3])
        : "r"(a[0]), "r"(a[1]), "r"(a[2]), "r"(a[3]), "r"(b[0]), "r"(b[1]));
}

__device__ __forceinline__ void split2(float v, __nv_bfloat16& a, __nv_bfloat16& b) {
    a = __float2bfloat16_rn(v);
    b = __float2bfloat16_rn(v - __bfloat162float(a));
}

// ---------------------------------------------------------------------------
// Conversion kernels
// ---------------------------------------------------------------------------
__global__ __launch_bounds__(256) void split_x(const float* __restrict__ x) {
    size_t i = ((size_t)blockIdx.x * 256 + threadIdx.x) * 4;
    float4 v = *(const float4*)(x + i);
    __nv_bfloat16 a[4], b[4];
    split2(v.x, a[0], b[0]);
    split2(v.y, a[1], b[1]);
    split2(v.z, a[2], b[2]);
    split2(v.w, a[3], b[3]);
    ushort4 pa, pb;
    pa.x = __bfloat16_as_ushort(a[0]); pa.y = __bfloat16_as_ushort(a[1]);
    pa.z = __bfloat16_as_ushort(a[2]); pa.w = __bfloat16_as_ushort(a[3]);
    pb.x = __bfloat16_as_ushort(b[0]); pb.y = __bfloat16_as_ushort(b[1]);
    pb.z = __bfloat16_as_ushort(b[2]); pb.w = __bfloat16_as_ushort(b[3]);
    *(ushort4*)(g_xs + i)  = pa;
    *(ushort4*)(g_xs2 + i) = pb;
}

// W1 [K][N] fp32 -> W1^T [N][K] bf16 (tiled transpose; single plane)
__global__ __launch_bounds__(256) void split_w1t(const float* __restrict__ W1) {
    __shared__ float t[32][33];
    const int k0 = blockIdx.x * 32;
    const int n0 = blockIdx.y * 32;
    const int tx = threadIdx.x;
    const int ty = threadIdx.y;
    #pragma unroll
    for (int j = 0; j < 4; j++)
        t[ty + 8 * j][tx] = W1[(size_t)(k0 + ty + 8 * j) * HID + n0 + tx];
    __syncthreads();
    #pragma unroll
    for (int j = 0; j < 4; j++)
        g_w1t[(size_t)(n0 + ty + 8 * j) * DIM + k0 + tx] =
            __float2bfloat16_rn(t[tx][ty + 8 * j]);
}

// W [K][64] fp32 -> W^T [64][K] bf16 x2 planes (tiled transpose + split)
__global__ __launch_bounds__(256) void split_wt(const float* __restrict__ W) {
    __shared__ float t[32][33];
    const int k0 = blockIdx.x * 32;
    const int n0 = blockIdx.y * 32;
    const int tx = threadIdx.x;
    const int ty = threadIdx.y;
    #pragma unroll
    for (int j = 0; j < 4; j++)
        t[ty + 8 * j][tx] = W[(size_t)(k0 + ty + 8 * j) * NEXP + n0 + tx];
    __syncthreads();
    #pragma unroll
    for (int j = 0; j < 4; j++) {
        __nv_bfloat16 a, b;
        split2(t[tx][ty + 8 * j], a, b);
        g_wt1[(size_t)(n0 + ty + 8 * j) * DIM + k0 + tx] = a;
        g_wt2[(size_t)(n0 + ty + 8 * j) * DIM + k0 + tx] = b;
    }
}

// ---------------------------------------------------------------------------
// GEMM1: single-pass bf16 HMMA computing z-partials directly (h never stored).
// CTA 128x128, 128 threads (4 warps 2Mx2N, warp 64x64), 3-stage cp.async,
// 60KB smem -> 2 CTAs/SM dephased. (Proven r12: 694us.)
// ---------------------------------------------------------------------------
#define G1_BM 128
#define G1_BN 128
#define G1_BK 32
#define PITCH 40                          // bf16 per smem row (80B)
#define STAGE_ROWS (G1_BM + G1_BN)        // 256 rows (A then B)
#define STAGE_B (STAGE_ROWS * PITCH * 2)  // 20480 bytes
#define NSTAGE 3
#define G1_SMEM (NSTAGE * STAGE_B)        // 61440
#define G1_NIT (DIM / G1_BK)              // 128

__global__ __launch_bounds__(128, 2) void gemm1_hmma(
    const float* __restrict__ bias, const float* __restrict__ W2
) {
    extern __shared__ char smem[];
    const uint32_t sbase = smem_u32(smem);

    const int tid  = threadIdx.x;
    const int warp = tid >> 5;
    const int lane = tid & 31;
    const int m0 = blockIdx.y * G1_BM;
    const int n0 = blockIdx.x * G1_BN;

    const int wm = (warp >> 1) * 64;
    const int wn = (warp & 1) * 64;

    const __nv_bfloat16* lsrc[8];
    uint32_t ldst[8];
    #pragma unroll
    for (int c = 0; c < 8; c++) {
        const int row = c * 32 + (tid >> 2);
        const int kc = tid & 3;
        lsrc[c] = (row < G1_BM ? g_xs + (size_t)(m0 + row) * DIM
                               : g_w1t + (size_t)(n0 + row - G1_BM) * DIM) + kc * 8;
        ldst[c] = (uint32_t)row * (PITCH * 2) + kc * 16;
    }

    float acc[4][8][4];
    #pragma unroll
    for (int i = 0; i < 4; i++)
        #pragma unroll
        for (int j = 0; j < 8; j++)
            #pragma unroll
            for (int q = 0; q < 4; q++) acc[i][j][q] = 0.f;

    auto load_stage = [&](int stage, int k0) {
        const uint32_t dst = sbase + stage * STAGE_B;
        #pragma unroll
        for (int c = 0; c < 8; c++)
            cp_async16(dst + ldst[c], lsrc[c] + k0);
        cp_commit();
    };

    load_stage(0, 0);
    load_stage(1, G1_BK);

    const int g = lane >> 3, r = lane & 7;

    for (int it = 0; it < G1_NIT; it++) {
        if (it + 2 < G1_NIT) {
            load_stage((it + 2) % NSTAGE, (it + 2) * G1_BK);
            cp_wait<2>();
        } else {
            cp_wait<0>();
        }
        __syncthreads();

        const uint32_t sb = sbase + (it % NSTAGE) * STAGE_B;

        #pragma unroll
        for (int s = 0; s < 2; s++) {
            uint32_t af[4][4];
            #pragma unroll
            for (int mb = 0; mb < 4; mb++) {
                const uint32_t off =
                    (uint32_t)(wm + mb * 16 + (g & 1) * 8 + r) * (PITCH * 2) + s * 32 + (g >> 1) * 16;
                ldmatrix_x4(af[mb][0], af[mb][1], af[mb][2], af[mb][3], sb + off);
            }
            uint32_t bf[8][2];
            #pragma unroll
            for (int nbp = 0; nbp < 4; nbp++) {
                const uint32_t off =
                    (uint32_t)(G1_BM + wn + nbp * 16 + (g >> 1) * 8 + r) * (PITCH * 2) + s * 32 + (g & 1) * 16;
                uint32_t q0, q1, q2, q3;
                ldmatrix_x4(q0, q1, q2, q3, sb + off);
                bf[nbp * 2][0] = q0; bf[nbp * 2][1] = q1;
                bf[nbp * 2 + 1][0] = q2; bf[nbp * 2 + 1][1] = q3;
            }
            #pragma unroll
            for (int mb = 0; mb < 4; mb++)
                #pragma unroll
                for (int nb = 0; nb < 8; nb++)
                    mma_bf16(acc[mb][nb], af[mb], bf[nb]);
        }
        __syncthreads();
    }

    // Epilogue: z_partial[token, ntile] = sum_cols relu(acc+bias)*W2[col]
    const int crow = lane >> 2;
    const int ccol = (lane & 3) * 2;
    float zrow[4][2];
    #pragma unroll
    for (int mb = 0; mb < 4; mb++) {
        float s0 = 0.f, s1 = 0.f;
        #pragma unroll
        for (int nb = 0; nb < 8; nb++) {
            const int gcol = n0 + wn + nb * 8 + ccol;
            const float b0 = bias[gcol], b1v = bias[gcol + 1];
            const float w0 = W2[gcol],  w1v = W2[gcol + 1];
            s0 = fmaf(fmaxf(acc[mb][nb][0] + b0, 0.f), w0, s0);
            s0 = fmaf(fmaxf(acc[mb][nb][1] + b1v, 0.f), w1v, s0);
            s1 = fmaf(fmaxf(acc[mb][nb][2] + b0, 0.f), w0, s1);
            s1 = fmaf(fmaxf(acc[mb][nb][3] + b1v, 0.f), w1v, s1);
        }
        zrow[mb][0] = s0;
        zrow[mb][1] = s1;
    }
    #pragma unroll
    for (int mb = 0; mb < 4; mb++)
        #pragma unroll
        for (int h2 = 0; h2 < 2; h2++) {
            float v = zrow[mb][h2];
            v += __shfl_xor_sync(0xFFFFFFFFu, v, 1);
            v += __shfl_xor_sync(0xFFFFFFFFu, v, 2);
            zrow[mb][h2] = v;
        }
    float* zsc = (float*)smem;
    if ((lane & 3) == 0) {
        #pragma unroll
        for (int mb = 0; mb < 4; mb++)
            #pragma unroll
            for (int h2 = 0; h2 < 2; h2++) {
                const int row = wm + mb * 16 + crow + h2 * 8;
                zsc[row * 2 + (warp & 1)] = zrow[mb][h2];
            }
    }
    __syncthreads();
    g_zp[(size_t)(m0 + tid) * NZT + blockIdx.x] = zsc[tid * 2] + zsc[tid * 2 + 1];
}

// ---------------------------------------------------------------------------
// GEMM2 on tensor cores: 2-way bf16 split, 3 passes (x1w1 + x1w2 + x2w1)
// into one fp32 accumulator. Retiled for full-chip coverage: CTA 64 tokens x
// 64 experts, grid 256, 61KB smem -> 2 CTAs/SM. DRAM-bound (~2.4TB/s stream).
// ---------------------------------------------------------------------------
#define L_BM 64
#define L_BK 32
#define L_ROWS (2 * L_BM + 2 * NEXP)      // A1,A2 (64 ea) + B1,B2 (64 ea) = 256
#define L_STAGE (L_ROWS * PITCH * 2)      // 20480
#define L_NST 3
#define L_SMEM (L_NST * L_STAGE)          // 61440
#define L_NIT (DIM / L_BK)                // 128

__global__ __launch_bounds__(128, 2) void gemm_logits_hmma() {
    extern __shared__ char smem[];
    const uint32_t sbase = smem_u32(smem);

    const int tid  = threadIdx.x;
    const int warp = tid >> 5;
    const int lane = tid & 31;
    const int m0 = blockIdx.x * L_BM;

    const int wm = (warp >> 1) * 32;   // 0 or 32
    const int wn = (warp & 1) * 32;    // 0 or 32

    // loads: 256 rows x 4 chunks = 1024 chunks, 8 per thread
    const __nv_bfloat16* lsrc[8];
    uint32_t ldst[8];
    #pragma unroll
    for (int c = 0; c < 8; c++) {
        const int row = c * 32 + (tid >> 2);
        const int kc = tid & 3;
        const __nv_bfloat16* base;
        if (row < 64)       base = g_xs  + (size_t)(m0 + row) * DIM;
        else if (row < 128) base = g_xs2 + (size_t)(m0 + row - 64) * DIM;
        else if (row < 192) base = g_wt1 + (size_t)(row - 128) * DIM;
        else                base = g_wt2 + (size_t)(row - 192) * DIM;
        lsrc[c] = base + kc * 8;
        ldst[c] = (uint32_t)row * (PITCH * 2) + kc * 16;
    }

    float acc[2][4][4];
    #pragma unroll
    for (int i = 0; i < 2; i++)
        #pragma unroll
        for (int j = 0; j < 4; j++)
            #pragma unroll
            for (int q = 0; q < 4; q++) acc[i][j][q] = 0.f;

    auto load_stage = [&](int stage, int k0) {
        const uint32_t dst = sbase + stage * L_STAGE;
        #pragma unroll
        for (int c = 0; c < 8; c++)
            cp_async16(dst + ldst[c], lsrc[c] + k0);
        cp_commit();
    };

    load_stage(0, 0);
    load_stage(1, L_BK);

    const int g = lane >> 3, r = lane & 7;

    for (int it = 0; it < L_NIT; it++) {
        if (it + 2 < L_NIT) {
            load_stage((it + 2) % L_NST, (it + 2) * L_BK);
            cp_wait<2>();
        } else {
            cp_wait<0>();
        }
        __syncthreads();

        const uint32_t sb = sbase + (it % L_NST) * L_STAGE;

        #pragma unroll
        for (int s = 0; s < 2; s++) {
            uint32_t a1f[2][4], a2f[2][4];
            #pragma unroll
            for (int mb = 0; mb < 2; mb++) {
                const uint32_t off =
                    (uint32_t)(wm + mb * 16 + (g & 1) * 8 + r) * (PITCH * 2) + s * 32 + (g >> 1) * 16;
                ldmatrix_x4(a1f[mb][0], a1f[mb][1], a1f[mb][2], a1f[mb][3], sb + off);
                ldmatrix_x4(a2f[mb][0], a2f[mb][1], a2f[mb][2], a2f[mb][3],
                            sb + off + 64 * (PITCH * 2));
            }
            uint32_t b1f[4][2], b2f[4][2];
            #pragma unroll
            for (int nbp = 0; nbp < 2; nbp++) {
                const uint32_t off =
                    (uint32_t)(128 + wn + nbp * 16 + (g >> 1) * 8 + r) * (PITCH * 2) + s * 32 + (g & 1) * 16;
                uint32_t q0, q1, q2, q3;
                ldmatrix_x4(q0, q1, q2, q3, sb + off);
                b1f[nbp * 2][0] = q0; b1f[nbp * 2][1] = q1;
                b1f[nbp * 2 + 1][0] = q2; b1f[nbp * 2 + 1][1] = q3;
                ldmatrix_x4(q0, q1, q2, q3, sb + off + 64 * (PITCH * 2));
                b2f[nbp * 2][0] = q0; b2f[nbp * 2][1] = q1;
                b2f[nbp * 2 + 1][0] = q2; b2f[nbp * 2 + 1][1] = q3;
            }
            #pragma unroll
            for (int mb = 0; mb < 2; mb++)
                #pragma unroll
                for (int nb = 0; nb < 4; nb++)
                    mma_bf16(acc[mb][nb], a1f[mb], b1f[nb]);
            #pragma unroll
            for (int mb = 0; mb < 2; mb++)
                #pragma unroll
                for (int nb = 0; nb < 4; nb++)
                    mma_bf16(acc[mb][nb], a1f[mb], b2f[nb]);
            #pragma unroll
            for (int mb = 0; mb < 2; mb++)
                #pragma unroll
                for (int nb = 0; nb < 4; nb++)
                    mma_bf16(acc[mb][nb], a2f[mb], b1f[nb]);
        }
        __syncthreads();
    }

    const int crow = lane >> 2;
    const int ccol = (lane & 3) * 2;
    #pragma unroll
    for (int mb = 0; mb < 2; mb++) {
        #pragma unroll
        for (int nb = 0; nb < 4; nb++) {
            const int col = wn + nb * 8 + ccol;
            const int row0 = m0 + wm + mb * 16 + crow;
            *(float2*)(g_logits + (size_t)row0 * NEXP + col) =
                make_float2(acc[mb][nb][0], acc[mb][nb][1]);
            *(float2*)(g_logits + (size_t)(row0 + 8) * NEXP + col) =
                make_float2(acc[mb][nb][2], acc[mb][nb][3]);
        }
    }
}

// ---------------------------------------------------------------------------
__global__ void reset_flags() { g_nflag = 0; g_nlflag = 0; }

// ---------------------------------------------------------------------------
// margin check: flag tokens whose top-4 adjacent logit gaps < GEPS (=15 sigma
// of the split-logit gap error ~2e-5). Expected ~5-20 tokens.
// ---------------------------------------------------------------------------
#define GEPS 3e-4f

__global__ __launch_bounds__(256) void check_margins() {
    const int warp = threadIdx.x >> 5;
    const int lane = threadIdx.x & 31;
    const int n = blockIdx.x * 8 + warp;

    const float* lp = g_logits + (size_t)n * NEXP;
    float c0 = lp[lane];
    float c1 = lp[lane + 32];

    float v[4];
    #pragma unroll
    for (int rnk = 0; rnk < 4; rnk++) {
        float vv;
        int idx;
        if (c1 > c0) { vv = c1; idx = lane + 32; }
        else         { vv = c0; idx = lane; }
        #pragma unroll
        for (int o = 16; o > 0; o >>= 1) {
            float ov = __shfl_xor_sync(0xFFFFFFFFu, vv, o);
            int   oi = __shfl_xor_sync(0xFFFFFFFFu, idx, o);
            if (ov > vv || (ov == vv && oi < idx)) { vv = ov; idx = oi; }
        }
        v[rnk] = vv;
        if (idx == lane)      c0 = -1e30f;
        if (idx == lane + 32) c1 = -1e30f;
    }
    if (lane == 0) {
        if (v[0] - v[1] < GEPS || v[1] - v[2] < GEPS || v[2] - v[3] < GEPS) {
            int slot = atomicAdd(&g_nlflag, 1);
            if (slot < FLAG_CAP) g_lflaglist[slot] = n;
        }
    }
}

// ---------------------------------------------------------------------------
// repair_logits: recompute flagged tokens' 64 logits with math bitwise
// identical to the proven fp32 Neumaier gemm_logits (serial 8-chunk flush).
// ---------------------------------------------------------------------------
__global__ __launch_bounds__(64) void repair_logits(
    const float* __restrict__ x, const float* __restrict__ W
) {
    const int e = threadIdx.x;   // expert
    const int cnt = min(g_nlflag, FLAG_CAP);
    for (int w = blockIdx.x; w < cnt; w += gridDim.x) {
        const int n = g_lflaglist[w];
        const float* xp = x + (size_t)n * DIM;
        float s = 0.f, comp = 0.f, part = 0.f;
        for (int k = 0; k < DIM; k++) {
            part = fmaf(xp[k], W[(size_t)k * NEXP + e], part);
            if ((k & 7) == 7) {
                const float t = __fadd_rn(s, part);
                const float err = (fabsf(s) >= fabsf(part))
                    ? __fadd_rn(__fsub_rn(s, t), part)
                    : __fadd_rn(__fsub_rn(part, t), s);
                comp = __fadd_rn(comp, err);
                s = t;
                part = 0.f;
            }
        }
        g_logits[(size_t)n * NEXP + e] = __fadd_rn(s, comp);
    }
}

// ---------------------------------------------------------------------------
// predictor: z = sum of 16 z-partials + b2 (fixed order) -> dynamic_k; flag
// near-boundary tokens (sigma_z ~1.1e-3; ZEPS = 0.005 ~ 4.5 sigma).
// ---------------------------------------------------------------------------
#define ZB 1.6094379124341003f
#define ZEPS 0.005f

__global__ __launch_bounds__(256) void predictor_k(const float* __restrict__ b2) {
    const int n = blockIdx.x * 256 + threadIdx.x;
    const float* zp = g_zp + (size_t)n * NZT;
    float z = b2[0];
    #pragma unroll
    for (int t = 0; t < NZT; t++) z += zp[t];
    float score = 1.0f / (1.0f + expf(-z));
    float kf = rintf(score * 3.0f) + 1.0f;
    kf = fminf(fmaxf(kf, 1.0f), 3.0f);
    g_kdyn[n] = (int)kf;
    if (fabsf(z) < ZEPS || fabsf(z - ZB) < ZEPS || fabsf(z + ZB) < ZEPS) {
        int slot = atomicAdd(&g_nflag, 1);
        if (slot < FLAG_CAP) g_flaglist[slot] = n;
    }
}

// ---------------------------------------------------------------------------
// repair phase A: batched accurate recompute of z-partials for flagged tokens.
// ---------------------------------------------------------------------------
#define RG_SMEM (RTOK * DIM * 4)   // 131072

__global__ __launch_bounds__(256) void repair_gemm(
    const float* __restrict__ x, const float* __restrict__ W1,
    const float* __restrict__ b1, const float* __restrict__ W2
) {
    extern __shared__ float xs[];   // [RTOK][DIM]
    __shared__ double zr[256];
    const int tid = threadIdx.x;
    const int cnt = min(g_nflag, FLAG_CAP);
    const int ngroups = (cnt + RTOK - 1) / RTOK;
    const int nwork = ngroups * RCB;

    for (int wk = blockIdx.x; wk < nwork; wk += gridDim.x) {
        const int grp = wk / RCB;
        const int cb = wk % RCB;
        const int g0 = grp * RTOK;
        const int nt = min(RTOK, cnt - g0);

        __syncthreads();
        for (int t = 0; t < nt; t++) {
            const int n = g_flaglist[g0 + t];
            const float4* src = (const float4*)(x + (size_t)n * DIM);
            float4* dst = (float4*)(xs + t * DIM);
            for (int j = tid; j < DIM / 4; j += 256) dst[j] = src[j];
        }
        __syncthreads();

        const int j = cb * 256 + tid;
        double aacc[RTOK];
        #pragma unroll
        for (int t = 0; t < RTOK; t++) aacc[t] = 0.0;

        for (int k0 = 0; k0 < DIM; k0 += 64) {
            float p[RTOK];
            #pragma unroll
            for (int t = 0; t < RTOK; t++) p[t] = 0.f;
            for (int k = 0; k < 64; k++) {
                const float w = W1[(size_t)(k0 + k) * HID + j];
                #pragma unroll
                for (int t = 0; t < RTOK; t++)
                    p[t] = fmaf(xs[t * DIM + k0 + k], w, p[t]);
            }
            #pragma unroll
            for (int t = 0; t < RTOK; t++) aacc[t] += (double)p[t];
        }

        const float w2j = W2[j];
        const float b1j = b1[j];
        for (int t = 0; t < nt; t++) {
            float h = fmaxf((float)(aacc[t] + (double)b1j), 0.f);
            zr[tid] = (double)h * (double)w2j;
            __syncthreads();
            for (int s = 128; s > 0; s >>= 1) {
                if (tid < s) zr[tid] += zr[tid + s];
                __syncthreads();
            }
            if (tid == 0) g_zpart[g0 + t][cb] = zr[0];
            __syncthreads();
        }
    }
}

// repair phase B: sum partials (fixed order), set dynamic_k for flagged tokens.
__global__ __launch_bounds__(256) void repair_finalize(const float* __restrict__ b2) {
    const int cnt = min(g_nflag, FLAG_CAP);
    const int i = blockIdx.x * 256 + threadIdx.x;
    if (i < cnt) {
        double z = (double)b2[0];
        #pragma unroll
        for (int c = 0; c < RCB; c++) z += g_zpart[i][c];
        float zf = (float)z;
        float score = 1.0f / (1.0f + expf(-zf));
        float kf = rintf(score * 3.0f) + 1.0f;
        kf = fminf(fmaxf(kf, 1.0f), 3.0f);
        g_kdyn[g_flaglist[i]] = (int)kf;
    }
}

// ---------------------------------------------------------------------------
// finalize: softmax/top-3 (rounded probs, lower-index ties)/mask/renorm
// ---------------------------------------------------------------------------
__global__ __launch_bounds__(256) void finalize(float* __restrict__ out) {
    const int warp = threadIdx.x >> 5;
    const int lane = threadIdx.x & 31;
    const int n = blockIdx.x * 8 + warp;

    const float* lp = g_logits + (size_t)n * NEXP;
    float l0 = lp[lane];
    float l1 = lp[lane + 32];

    float m = fmaxf(l0, l1);
    #pragma unroll
    for (int o = 16; o > 0; o >>= 1) m = fmaxf(m, __shfl_xor_sync(0xFFFFFFFFu, m, o));
    float e0 = expf(l0 - m);
    float e1 = expf(l1 - m);
    float s = e0 + e1;
    #pragma unroll
    for (int o = 16; o > 0; o >>= 1) s += __shfl_xor_sync(0xFFFFFFFFu, s, o);

    float p0 = e0 / s;
    float p1 = e1 / s;

    float c0 = p0, c1 = p1;
    float tv[TOPK];
    int   ti[TOPK];
    #pragma unroll
    for (int r = 0; r < TOPK; r++) {
        float v;
        int idx;
        if (c1 > c0) { v = c1; idx = lane + 32; }
        else         { v = c0; idx = lane; }
        #pragma unroll
        for (int o = 16; o > 0; o >>= 1) {
            float ov = __shfl_xor_sync(0xFFFFFFFFu, v, o);
            int   oi = __shfl_xor_sync(0xFFFFFFFFu, idx, o);
            if (ov > v || (ov == v && oi < idx)) { v = ov; idx = oi; }
        }
        tv[r] = v;
        ti[r] = idx;
        if (idx == lane)      c0 = -1.0f;
        if (idx == lane + 32) c1 = -1.0f;
    }

    const int k = g_kdyn[n];

    float msum = 0.f;
    #pragma unroll
    for (int r = 0; r < TOPK; r++)
        if (r < k) msum += tv[r];
    const float denom = msum + 1e-8f;

    if (lane < TOPK) {
        float w = (lane < k ? tv[lane] : 0.f) / denom;
        out[OFF_W + (size_t)n * TOPK + lane] = w;
        out[OFF_I + (size_t)n * TOPK + lane] = (float)ti[lane];
    }

    float m0v = 0.f, m1v = 0.f;
    #pragma unroll
    for (int r = 0; r < TOPK; r++) {
        if (r < k) {
            if (ti[r] == lane)      m0v = 1.0f;
            if (ti[r] == lane + 32) m1v = 1.0f;
        }
    }
    out[OFF_M + (size_t)n * NEXP + lane]      = m0v;
    out[OFF_M + (size_t)n * NEXP + lane + 32] = m1v;

    if (lane == 0) out[OFF_K + n] = (float)k;
}

// ---------------------------------------------------------------------------
extern "C" void kernel_launch(void* const* d_in, const int* in_sizes, int n_in,
                              void* d_out, int out_size) {
    const float* x  = (const float*)d_in[0];
    const float* W  = (const float*)d_in[1];
    const float* W1 = (const float*)d_in[2];
    const float* b1 = (const float*)d_in[3];
    const float* W2 = (const float*)d_in[4];
    const float* b2 = (const float*)d_in[5];
    float* out = (float*)d_out;

    static int smem_set = 0;
    if (!smem_set) {
        cudaFuncSetAttribute(gemm1_hmma, cudaFuncAttributeMaxDynamicSharedMemorySize, G1_SMEM);
        cudaFuncSetAttribute(gemm_logits_hmma, cudaFuncAttributeMaxDynamicSharedMemorySize, L_SMEM);
        cudaFuncSetAttribute(repair_gemm, cudaFuncAttributeMaxDynamicSharedMemorySize, RG_SMEM);
        smem_set = 1;
    }

    // gemm_logits_hmma at launch index 3 (the auto-ncu capture target).
    split_x<<<(int)(XPLANE / (256 * 4)), 256>>>(x);                          // 0
    split_w1t<<<dim3(DIM / 32, HID / 32), dim3(32, 8)>>>(W1);                // 1
    split_wt<<<dim3(DIM / 32, NEXP / 32), dim3(32, 8)>>>(W);                 // 2
    gemm_logits_hmma<<<NTOK / L_BM, 128, L_SMEM>>>();                        // 3 <- profiled
    gemm1_hmma<<<dim3(HID / G1_BN, NTOK / G1_BM), 128, G1_SMEM>>>(b1, W2);   // 4
    reset_flags<<<1, 1>>>();                                                 // 5
    predictor_k<<<NTOK / 256, 256>>>(b2);                                    // 6
    check_margins<<<NTOK / 8, 256>>>();                                      // 7
    repair_gemm<<<256, 256, RG_SMEM>>>(x, W1, b1, W2);                       // 8
    repair_finalize<<<FLAG_CAP / 256, 256>>>(b2);                            // 9
    repair_logits<<<64, 64>>>(x, W);                                         // 10
    finalize<<<NTOK / 8, 256>>>(out);                                        // 11
}

// round 17
// speedup vs baseline: 1.5363x; 1.5363x over previous
#include <cuda_runtime.h>
#include <cuda_bf16.h>
#include <math.h>
#include <stdint.h>

// Problem dims
#define NTOK 16384      // B*S
#define DIM  4096       // D (K of both GEMMs)
#define HID  2048       // H (N of GEMM1)
#define NEXP 64
#define TOPK 3

// Output layout (float32, concatenated flattened reference outputs)
#define OFF_W 0
#define OFF_I (NTOK * TOPK)
#define OFF_M (2 * NTOK * TOPK)
#define OFF_K (2 * NTOK * TOPK + NTOK * NEXP)

// Scratch (device globals)
#define XPLANE ((size_t)NTOK * DIM)
#define WPLANE ((size_t)HID * DIM)
#define FLAG_CAP 4096
#define RTOK 8
#define RCB  8           // repair column blocks (HID/256)
#define NZT  16          // z-partial tiles (HID/128)
__device__ __align__(16) __nv_bfloat16 g_xs[XPLANE];    // 134 MB: x as bf16
__device__ __align__(16) __nv_bfloat16 g_w1t[WPLANE];   // 17 MB: W1^T bf16 [N][K]
__device__ float g_zp[(size_t)NTOK * NZT];              // 1 MB: z partials per n-tile
__device__ float g_lpart[2][(size_t)NTOK * NEXP];       // 8 MB: split-K logit partials
__device__ int   g_kdyn[NTOK];
__device__ int   g_nflag;
__device__ int   g_flaglist[FLAG_CAP];
__device__ double g_zpart[FLAG_CAP][RCB];

// ---------------------------------------------------------------------------
// PTX helpers (baseline sm_80+ ISA)
// ---------------------------------------------------------------------------
__device__ __forceinline__ uint32_t smem_u32(const void* p) {
    uint32_t a;
    asm("{ .reg .u64 t; cvta.to.shared.u64 t, %1; cvt.u32.u64 %0, t; }" : "=r"(a) : "l"(p));
    return a;
}
__device__ __forceinline__ void cp_async16(uint32_t dst, const void* src) {
    asm volatile("cp.async.cg.shared.global [%0], [%1], 16;" :: "r"(dst), "l"(src));
}
__device__ __forceinline__ void cp_commit() {
    asm volatile("cp.async.commit_group;");
}
template <int N>
__device__ __forceinline__ void cp_wait() {
    asm volatile("cp.async.wait_group %0;" :: "n"(N));
}
__device__ __forceinline__ void ldmatrix_x4(uint32_t& r0, uint32_t& r1, uint32_t& r2, uint32_t& r3,
                                            uint32_t addr) {
    asm volatile("ldmatrix.sync.aligned.m8n8.x4.shared.b16 {%0,%1,%2,%3}, [%4];"
                 : "=r"(r0), "=r"(r1), "=r"(r2), "=r"(r3) : "r"(addr));
}
__device__ __forceinline__ void mma_bf16(float* c, const uint32_t* a, const uint32_t* b) {
    asm volatile(
        "mma.sync.aligned.m16n8k16.row.col.f32.bf16.bf16.f32 "
        "{%0,%1,%2,%3}, {%4,%5,%6,%7}, {%8,%9}, {%0,%1,%2,%3};"
        : "+f"(c[0]), "+f"(c[1]), "+f"(c[2]), "+f"(c[3])
        : "r"(a[0]), "r"(a[1]), "r"(a[2]), "r"(a[3]), "r"(b[0]), "r"(b[1]));
}

// ---------------------------------------------------------------------------
// Conversion kernels (single bf16 plane)
// ---------------------------------------------------------------------------
__global__ __launch_bounds__(256) void split_x(const float* __restrict__ x) {
    size_t i = ((size_t)blockIdx.x * 256 + threadIdx.x) * 4;
    float4 v = *(const float4*)(x + i);
    ushort4 p;
    p.x = __bfloat16_as_ushort(__float2bfloat16_rn(v.x));
    p.y = __bfloat16_as_ushort(__float2bfloat16_rn(v.y));
    p.z = __bfloat16_as_ushort(__float2bfloat16_rn(v.z));
    p.w = __bfloat16_as_ushort(__float2bfloat16_rn(v.w));
    *(ushort4*)(g_xs + i) = p;
}

// W1 [K][N] fp32 -> W1^T [N][K] bf16 (tiled transpose)
__global__ __launch_bounds__(256) void split_w1t(const float* __restrict__ W1) {
    __shared__ float t[32][33];
    const int k0 = blockIdx.x * 32;
    const int n0 = blockIdx.y * 32;
    const int tx = threadIdx.x;
    const int ty = threadIdx.y;
    #pragma unroll
    for (int j = 0; j < 4; j++)
        t[ty + 8 * j][tx] = W1[(size_t)(k0 + ty + 8 * j) * HID + n0 + tx];
    __syncthreads();
    #pragma unroll
    for (int j = 0; j < 4; j++)
        g_w1t[(size_t)(n0 + ty + 8 * j) * DIM + k0 + tx] =
            __float2bfloat16_rn(t[tx][ty + 8 * j]);
}

// ---------------------------------------------------------------------------
// GEMM1: single-pass bf16 HMMA computing z-partials directly (h never stored).
// CTA 128x128, BK=32, 128 threads (4 warps as 2Mx2N), warp tile 64x64.
// 3-stage cp.async, 60KB smem -> 2 CTAs/SM dephased. (Proven r12: 694us.)
// ---------------------------------------------------------------------------
#define G1_BM 128
#define G1_BN 128
#define G1_BK 32
#define PITCH 40                          // bf16 per smem row (80B)
#define STAGE_ROWS (G1_BM + G1_BN)        // 256 rows (A then B)
#define STAGE_B (STAGE_ROWS * PITCH * 2)  // 20480 bytes
#define NSTAGE 3
#define G1_SMEM (NSTAGE * STAGE_B)        // 61440
#define G1_NIT (DIM / G1_BK)              // 128

__global__ __launch_bounds__(128, 2) void gemm1_hmma(
    const float* __restrict__ bias, const float* __restrict__ W2
) {
    extern __shared__ char smem[];
    const uint32_t sbase = smem_u32(smem);

    const int tid  = threadIdx.x;
    const int warp = tid >> 5;
    const int lane = tid & 31;
    const int m0 = blockIdx.y * G1_BM;
    const int n0 = blockIdx.x * G1_BN;

    const int wm = (warp >> 1) * 64;
    const int wn = (warp & 1) * 64;

    const __nv_bfloat16* lsrc[8];
    uint32_t ldst[8];
    #pragma unroll
    for (int c = 0; c < 8; c++) {
        const int row = c * 32 + (tid >> 2);
        const int kc = tid & 3;
        lsrc[c] = (row < G1_BM ? g_xs + (size_t)(m0 + row) * DIM
                               : g_w1t + (size_t)(n0 + row - G1_BM) * DIM) + kc * 8;
        ldst[c] = (uint32_t)row * (PITCH * 2) + kc * 16;
    }

    float acc[4][8][4];
    #pragma unroll
    for (int i = 0; i < 4; i++)
        #pragma unroll
        for (int j = 0; j < 8; j++)
            #pragma unroll
            for (int q = 0; q < 4; q++) acc[i][j][q] = 0.f;

    auto load_stage = [&](int stage, int k0) {
        const uint32_t dst = sbase + stage * STAGE_B;
        #pragma unroll
        for (int c = 0; c < 8; c++)
            cp_async16(dst + ldst[c], lsrc[c] + k0);
        cp_commit();
    };

    load_stage(0, 0);
    load_stage(1, G1_BK);

    const int g = lane >> 3, r = lane & 7;

    for (int it = 0; it < G1_NIT; it++) {
        if (it + 2 < G1_NIT) {
            load_stage((it + 2) % NSTAGE, (it + 2) * G1_BK);
            cp_wait<2>();
        } else {
            cp_wait<0>();
        }
        __syncthreads();

        const uint32_t sb = sbase + (it % NSTAGE) * STAGE_B;

        #pragma unroll
        for (int s = 0; s < 2; s++) {
            uint32_t af[4][4];
            #pragma unroll
            for (int mb = 0; mb < 4; mb++) {
                const uint32_t off =
                    (uint32_t)(wm + mb * 16 + (g & 1) * 8 + r) * (PITCH * 2) + s * 32 + (g >> 1) * 16;
                ldmatrix_x4(af[mb][0], af[mb][1], af[mb][2], af[mb][3], sb + off);
            }
            uint32_t bf[8][2];
            #pragma unroll
            for (int nbp = 0; nbp < 4; nbp++) {
                const uint32_t off =
                    (uint32_t)(G1_BM + wn + nbp * 16 + (g >> 1) * 8 + r) * (PITCH * 2) + s * 32 + (g & 1) * 16;
                uint32_t q0, q1, q2, q3;
                ldmatrix_x4(q0, q1, q2, q3, sb + off);
                bf[nbp * 2][0] = q0; bf[nbp * 2][1] = q1;
                bf[nbp * 2 + 1][0] = q2; bf[nbp * 2 + 1][1] = q3;
            }
            #pragma unroll
            for (int mb = 0; mb < 4; mb++)
                #pragma unroll
                for (int nb = 0; nb < 8; nb++)
                    mma_bf16(acc[mb][nb], af[mb], bf[nb]);
        }
        __syncthreads();
    }

    // Epilogue: z_partial[token, ntile] = sum_cols relu(acc+bias)*W2[col]
    const int crow = lane >> 2;
    const int ccol = (lane & 3) * 2;
    float zrow[4][2];
    #pragma unroll
    for (int mb = 0; mb < 4; mb++) {
        float s0 = 0.f, s1 = 0.f;
        #pragma unroll
        for (int nb = 0; nb < 8; nb++) {
            const int gcol = n0 + wn + nb * 8 + ccol;
            const float b0 = bias[gcol], b1v = bias[gcol + 1];
            const float w0 = W2[gcol],  w1v = W2[gcol + 1];
            s0 = fmaf(fmaxf(acc[mb][nb][0] + b0, 0.f), w0, s0);
            s0 = fmaf(fmaxf(acc[mb][nb][1] + b1v, 0.f), w1v, s0);
            s1 = fmaf(fmaxf(acc[mb][nb][2] + b0, 0.f), w0, s1);
            s1 = fmaf(fmaxf(acc[mb][nb][3] + b1v, 0.f), w1v, s1);
        }
        zrow[mb][0] = s0;
        zrow[mb][1] = s1;
    }
    #pragma unroll
    for (int mb = 0; mb < 4; mb++)
        #pragma unroll
        for (int h2 = 0; h2 < 2; h2++) {
            float v = zrow[mb][h2];
            v += __shfl_xor_sync(0xFFFFFFFFu, v, 1);
            v += __shfl_xor_sync(0xFFFFFFFFu, v, 2);
            zrow[mb][h2] = v;
        }
    float* zsc = (float*)smem;
    if ((lane & 3) == 0) {
        #pragma unroll
        for (int mb = 0; mb < 4; mb++)
            #pragma unroll
            for (int h2 = 0; h2 < 2; h2++) {
                const int row = wm + mb * 16 + crow + h2 * 8;
                zsc[row * 2 + (warp & 1)] = zrow[mb][h2];
            }
    }
    __syncthreads();
    g_zp[(size_t)(m0 + tid) * NZT + blockIdx.x] = zsc[tid * 2] + zsc[tid * 2 + 1];
}

// ---------------------------------------------------------------------------
// GEMM2 (high accuracy, fp32-only, split-K x2): g_lpart[kh] = x @ W over half K.
// 64-token x 64-expert tiles, 4x4 per thread, grid 512. fp32 partials over
// 8-term chunks + Neumaier-compensated accumulation. (Proven r13.)
// ---------------------------------------------------------------------------
__global__ __launch_bounds__(256) void gemm_logits(
    const float* __restrict__ A, const float* __restrict__ B
) {
    __shared__ float As_t[32][64];
    __shared__ float Bs[32][64];

    const int tid = threadIdx.x;
    const int m0 = blockIdx.x * 64;
    const int kh = blockIdx.y;           // K half: 0 or 1
    const int kbeg = kh * (DIM / 2);
    const int kend = kbeg + (DIM / 2);
    float* outp = g_lpart[kh];

    const int tg4 = (tid >> 4) * 4;
    const int eg4 = (tid & 15) * 4;

    float accs[4][4], accc[4][4];
    #pragma unroll
    for (int i = 0; i < 4; i++)
        #pragma unroll
        for (int j = 0; j < 4; j++) { accs[i][j] = 0.f; accc[i][j] = 0.f; }

    const int ar = tid >> 3;
    const int ac = (tid & 7) * 4;

    for (int k0 = kbeg; k0 < kend; k0 += 32) {
        __syncthreads();
        #pragma unroll
        for (int it = 0; it < 2; it++) {
            const int r = it * 32 + ar;
            float4 av = *(const float4*)(A + (size_t)(m0 + r) * DIM + k0 + ac);
            As_t[ac + 0][r] = av.x;
            As_t[ac + 1][r] = av.y;
            As_t[ac + 2][r] = av.z;
            As_t[ac + 3][r] = av.w;
        }
        #pragma unroll
        for (int it = 0; it < 2; it++) {
            const int f = tid * 2 + it;
            const int kk = f >> 4;
            const int e4 = (f & 15) * 4;
            *(float4*)&Bs[kk][e4] = *(const float4*)(B + (size_t)(k0 + kk) * NEXP + e4);
        }
        __syncthreads();

        float part[4][4];
        #pragma unroll
        for (int i = 0; i < 4; i++)
            #pragma unroll
            for (int j = 0; j < 4; j++) part[i][j] = 0.f;

        #pragma unroll
        for (int kk = 0; kk < 32; kk++) {
            float4 a = *(const float4*)&As_t[kk][tg4];
            float4 b = *(const float4*)&Bs[kk][eg4];
            float av[4] = {a.x, a.y, a.z, a.w};
            float bv[4] = {b.x, b.y, b.z, b.w};
            #pragma unroll
            for (int i = 0; i < 4; i++)
                #pragma unroll
                for (int j = 0; j < 4; j++)
                    part[i][j] = fmaf(av[i], bv[j], part[i][j]);
            if ((kk & 7) == 7) {
                #pragma unroll
                for (int i = 0; i < 4; i++)
                    #pragma unroll
                    for (int j = 0; j < 4; j++) {
                        const float p = part[i][j];
                        const float s0 = accs[i][j];
                        const float t = __fadd_rn(s0, p);
                        const float e = (fabsf(s0) >= fabsf(p))
                            ? __fadd_rn(__fsub_rn(s0, t), p)
                            : __fadd_rn(__fsub_rn(p, t), s0);
                        accc[i][j] = __fadd_rn(accc[i][j], e);
                        accs[i][j] = t;
                        part[i][j] = 0.f;
                    }
            }
        }
    }

    #pragma unroll
    for (int i = 0; i < 4; i++) {
        const int row = m0 + tg4 + i;
        #pragma unroll
        for (int j = 0; j < 4; j++)
            outp[(size_t)row * NEXP + eg4 + j] = __fadd_rn(accs[i][j], accc[i][j]);
    }
}

// ---------------------------------------------------------------------------
__global__ void reset_flags() { g_nflag = 0; }

// ---------------------------------------------------------------------------
// predictor: z = sum of 16 z-partials + b2 (fixed order) -> dynamic_k; flag
// near-boundary tokens. ZEPS = 0.005 ~ 4.5 sigma of the bf16-induced z error
// (sigma ~1.1e-3): P(miss) ~ 1e-4 total.
// ---------------------------------------------------------------------------
#define ZB 1.6094379124341003f
#define ZEPS 0.005f

__global__ __launch_bounds__(256) void predictor_k(const float* __restrict__ b2) {
    const int n = blockIdx.x * 256 + threadIdx.x;
    const float* zp = g_zp + (size_t)n * NZT;
    float z = b2[0];
    #pragma unroll
    for (int t = 0; t < NZT; t++) z += zp[t];
    float score = 1.0f / (1.0f + expf(-z));
    float kf = rintf(score * 3.0f) + 1.0f;
    kf = fminf(fmaxf(kf, 1.0f), 3.0f);
    g_kdyn[n] = (int)kf;
    if (fabsf(z) < ZEPS || fabsf(z - ZB) < ZEPS || fabsf(z + ZB) < ZEPS) {
        int slot = atomicAdd(&g_nflag, 1);
        if (slot < FLAG_CAP) g_flaglist[slot] = n;
    }
}

// ---------------------------------------------------------------------------
// repair phase A: batched accurate recompute of z-partials for flagged tokens.
// (RTOK=8, 128KB smem: proven r10 config.)
// ---------------------------------------------------------------------------
#define RG_SMEM (RTOK * DIM * 4)   // 131072

__global__ __launch_bounds__(256) void repair_gemm(
    const float* __restrict__ x, const float* __restrict__ W1,
    const float* __restrict__ b1, const float* __restrict__ W2
) {
    extern __shared__ float xs[];   // [RTOK][DIM]
    __shared__ double zr[256];
    const int tid = threadIdx.x;
    const int cnt = min(g_nflag, FLAG_CAP);
    const int ngroups = (cnt + RTOK - 1) / RTOK;
    const int nwork = ngroups * RCB;

    for (int wk = blockIdx.x; wk < nwork; wk += gridDim.x) {
        const int grp = wk / RCB;
        const int cb = wk % RCB;
        const int g0 = grp * RTOK;
        const int nt = min(RTOK, cnt - g0);

        __syncthreads();
        for (int t = 0; t < nt; t++) {
            const int n = g_flaglist[g0 + t];
            const float4* src = (const float4*)(x + (size_t)n * DIM);
            float4* dst = (float4*)(xs + t * DIM);
            for (int j = tid; j < DIM / 4; j += 256) dst[j] = src[j];
        }
        __syncthreads();

        const int j = cb * 256 + tid;
        double aacc[RTOK];
        #pragma unroll
        for (int t = 0; t < RTOK; t++) aacc[t] = 0.0;

        for (int k0 = 0; k0 < DIM; k0 += 64) {
            float p[RTOK];
            #pragma unroll
            for (int t = 0; t < RTOK; t++) p[t] = 0.f;
            for (int k = 0; k < 64; k++) {
                const float w = W1[(size_t)(k0 + k) * HID + j];
                #pragma unroll
                for (int t = 0; t < RTOK; t++)
                    p[t] = fmaf(xs[t * DIM + k0 + k], w, p[t]);
            }
            #pragma unroll
            for (int t = 0; t < RTOK; t++) aacc[t] += (double)p[t];
        }

        const float w2j = W2[j];
        const float b1j = b1[j];
        for (int t = 0; t < nt; t++) {
            float h = fmaxf((float)(aacc[t] + (double)b1j), 0.f);
            zr[tid] = (double)h * (double)w2j;
            __syncthreads();
            for (int s = 128; s > 0; s >>= 1) {
                if (tid < s) zr[tid] += zr[tid + s];
                __syncthreads();
            }
            if (tid == 0) g_zpart[g0 + t][cb] = zr[0];
            __syncthreads();
        }
    }
}

// repair phase B: sum partials (fixed order), set dynamic_k for flagged tokens.
__global__ __launch_bounds__(256) void repair_finalize(const float* __restrict__ b2) {
    const int cnt = min(g_nflag, FLAG_CAP);
    const int i = blockIdx.x * 256 + threadIdx.x;
    if (i < cnt) {
        double z = (double)b2[0];
        #pragma unroll
        for (int c = 0; c < RCB; c++) z += g_zpart[i][c];
        float zf = (float)z;
        float score = 1.0f / (1.0f + expf(-zf));
        float kf = rintf(score * 3.0f) + 1.0f;
        kf = fminf(fmaxf(kf, 1.0f), 3.0f);
        g_kdyn[g_flaglist[i]] = (int)kf;
    }
}

// ---------------------------------------------------------------------------
// finalize: sum split-K logits, softmax/top-3 (rounded probs, lower-index
// ties)/mask/renorm. One warp per token.
// ---------------------------------------------------------------------------
__global__ __launch_bounds__(256) void finalize(float* __restrict__ out) {
    const int warp = threadIdx.x >> 5;
    const int lane = threadIdx.x & 31;
    const int n = blockIdx.x * 8 + warp;

    const float* lpA = g_lpart[0] + (size_t)n * NEXP;
    const float* lpB = g_lpart[1] + (size_t)n * NEXP;
    float l0 = __fadd_rn(lpA[lane],      lpB[lane]);
    float l1 = __fadd_rn(lpA[lane + 32], lpB[lane + 32]);

    float m = fmaxf(l0, l1);
    #pragma unroll
    for (int o = 16; o > 0; o >>= 1) m = fmaxf(m, __shfl_xor_sync(0xFFFFFFFFu, m, o));
    float e0 = expf(l0 - m);
    float e1 = expf(l1 - m);
    float s = e0 + e1;
    #pragma unroll
    for (int o = 16; o > 0; o >>= 1) s += __shfl_xor_sync(0xFFFFFFFFu, s, o);

    float p0 = e0 / s;
    float p1 = e1 / s;

    float c0 = p0, c1 = p1;
    float tv[TOPK];
    int   ti[TOPK];
    #pragma unroll
    for (int r = 0; r < TOPK; r++) {
        float v;
        int idx;
        if (c1 > c0) { v = c1; idx = lane + 32; }
        else         { v = c0; idx = lane; }
        #pragma unroll
        for (int o = 16; o > 0; o >>= 1) {
            float ov = __shfl_xor_sync(0xFFFFFFFFu, v, o);
            int   oi = __shfl_xor_sync(0xFFFFFFFFu, idx, o);
            if (ov > v || (ov == v && oi < idx)) { v = ov; idx = oi; }
        }
        tv[r] = v;
        ti[r] = idx;
        if (idx == lane)      c0 = -1.0f;
        if (idx == lane + 32) c1 = -1.0f;
    }

    const int k = g_kdyn[n];

    float msum = 0.f;
    #pragma unroll
    for (int r = 0; r < TOPK; r++)
        if (r < k) msum += tv[r];
    const float denom = msum + 1e-8f;

    if (lane < TOPK) {
        float w = (lane < k ? tv[lane] : 0.f) / denom;
        out[OFF_W + (size_t)n * TOPK + lane] = w;
        out[OFF_I + (size_t)n * TOPK + lane] = (float)ti[lane];
    }

    float m0v = 0.f, m1v = 0.f;
    #pragma unroll
    for (int r = 0; r < TOPK; r++) {
        if (r < k) {
            if (ti[r] == lane)      m0v = 1.0f;
            if (ti[r] == lane + 32) m1v = 1.0f;
        }
    }
    out[OFF_M + (size_t)n * NEXP + lane]      = m0v;
    out[OFF_M + (size_t)n * NEXP + lane + 32] = m1v;

    if (lane == 0) out[OFF_K + n] = (float)k;
}

// ---------------------------------------------------------------------------
extern "C" void kernel_launch(void* const* d_in, const int* in_sizes, int n_in,
                              void* d_out, int out_size) {
    const float* x  = (const float*)d_in[0];
    const float* W  = (const float*)d_in[1];
    const float* W1 = (const float*)d_in[2];
    const float* b1 = (const float*)d_in[3];
    const float* W2 = (const float*)d_in[4];
    const float* b2 = (const float*)d_in[5];
    float* out = (float*)d_out;

    static int smem_set = 0;
    if (!smem_set) {
        cudaFuncSetAttribute(gemm1_hmma, cudaFuncAttributeMaxDynamicSharedMemorySize, G1_SMEM);
        cudaFuncSetAttribute(repair_gemm, cudaFuncAttributeMaxDynamicSharedMemorySize, RG_SMEM);
        smem_set = 1;
    }

    // gemm_logits at launch index 3 (the auto-ncu capture target).
    split_x<<<(int)(XPLANE / (256 * 4)), 256>>>(x);                          // 0
    split_w1t<<<dim3(DIM / 32, HID / 32), dim3(32, 8)>>>(W1);                // 1
    gemm1_hmma<<<dim3(HID / G1_BN, NTOK / G1_BM), 128, G1_SMEM>>>(b1, W2);   // 2
    gemm_logits<<<dim3(NTOK / 64, 2), 256>>>(x, W);                          // 3 <- profiled
    reset_flags<<<1, 1>>>();                                                 // 4
    predictor_k<<<NTOK / 256, 256>>>(b2);                                    // 5
    repair_gemm<<<256, 256, RG_SMEM>>>(x, W1, b1, W2);                       // 6
    repair_finalize<<<FLAG_CAP / 256, 256>>>(b2);                            // 7
    finalize<<<NTOK / 8, 256>>>(out);                                        // 8
}